// round 15
// baseline (speedup 1.0000x reference)
#include <cuda_runtime.h>
#include <cooperative_groups.h>
#include <math.h>

namespace cg = cooperative_groups;

#define NN 2048
#define MM 32
#define NMOM 8                 // moments M_0..M_7 (degree-7 erf series)
#define TB 1024                // threads per CTA (32 warps)
#define NW 32

// A[m][p] = C[(m+p-1)/2] * binom(m+p, m) * (-1)^p for (m+p) odd <= 7, else 0.
// 0.5*erf(d) ~ C0 d + C1 d^3 + C2 d^5 + C3 d^7  (|d| <= 0.3536, trunc ~5e-7 rel)
__device__ __constant__ float d_A[NMOM][NMOM] = {
  {0.f,-0.5641895835477563f,0.f, 0.18806319451591878f,0.f,-0.05641895835477563f,0.f, 0.013433085322565627f},
  {0.5641895835477563f,0.f,-0.5641895835477563f,0.f, 0.28209479177387815f,0.f,-0.09403159725795939f,0.f},
  {0.f, 0.5641895835477563f,0.f,-0.5641895835477563f,0.f, 0.28209479177387817f,0.f,0.f},
  {-0.18806319451591878f,0.f, 0.5641895835477563f,0.f,-0.47015798628979696f,0.f,0.f,0.f},
  {0.f,-0.28209479177387815f,0.f, 0.47015798628979696f,0.f,0.f,0.f,0.f},
  {0.05641895835477563f,0.f,-0.28209479177387817f,0.f,0.f,0.f,0.f,0.f},
  {0.f, 0.09403159725795939f,0.f,0.f,0.f,0.f,0.f,0.f},
  {-0.013433085322565627f,0.f,0.f,0.f,0.f,0.f,0.f,0.f}
};

template <int CLUS>
__global__ void __launch_bounds__(TB, 1)
fused(const float* __restrict__ risk,
      const float* __restrict__ expr,
      const float* __restrict__ tr,
      const float* __restrict__ ev,
      const float* __restrict__ sigma,
      float* __restrict__ out) {
    constexpr int EPT = (NN * MM) / (CLUS * TB);   // 8 @ CLUS=8, 4 @ CLUS=16
    constexpr int RP  = CLUS + 1;                  // padded rank stride (odd -> no bank conflicts)
    cg::cluster_group cluster = cg::this_cluster();
    const int tid  = threadIdx.x;
    const int warp = tid >> 5, lane = tid & 31;
    const int myrank = blockIdx.x;                 // single cluster == grid

    __shared__ float smom[16][NMOM][MM];           // 16 KB  (two-step block reduce)
    __shared__ float smax[16][MM];                 // 2 KB
    __shared__ float recv_mom[NMOM][MM][RP];       // pushed by all ranks
    __shared__ float recv_max[MM][RP];
    __shared__ float recv_loss[16];                // pushed into CTA 0 only
    __shared__ float sfp[NMOM][MM];                // f^q per column
    __shared__ float sM[NMOM][MM];                 // cluster-wide raw moments
    __shared__ float sbb[NMOM + 1][MM];            // b_0..b_7, row NMOM = W
    __shared__ float wred[NW], wred2[NW];
    __shared__ __align__(8) unsigned long long mbar;

    uint32_t mbar_addr;
    asm("{ .reg .u64 t; cvta.to.shared.u64 t, %1; cvt.u32.u64 %0, t; }"
        : "=r"(mbar_addr) : "l"(&mbar));
    if (myrank == 0 && tid == 0)
        asm volatile("mbarrier.init.shared.b64 [%0], %1;" :: "r"(mbar_addr), "r"(CLUS) : "memory");

    const float sigv = sigma[0];
    const int   base = myrank * (TB * EPT) + tid;  // lane = column (stride 1024)

    // ---------------- Phase 1: moments + max + rv*ev over EPT elements ----------------
    float w[EPT], T[EPT], evv[EPT];
    float mx = -1e30f, rp = 0.0f;
    float m[NMOM];
#pragma unroll
    for (int q = 0; q < NMOM; ++q) m[q] = 0.0f;

#pragma unroll
    for (int e = 0; e < EPT; ++e) {
        const int idx = base + e * TB;
        float rv = risk[idx];
        float d  = expr[idx] - tr[idx];
        evv[e] = ev[idx];
        T[e]   = __expf(d);
        w[e]   = __expf(rv);
        mx = fmaxf(mx, d);
        rp = fmaf(rv, evv[e], rp);
        float p = w[e];
        m[0] += p;
#pragma unroll
        for (int q = 1; q < NMOM; ++q) { p *= T[e]; m[q] += p; }
    }
    // rv*ev partial: warp reduce now, block-combine inside the barrier window
#pragma unroll
    for (int o = 16; o > 0; o >>= 1) rp += __shfl_down_sync(0xffffffffu, rp, o);
    if (lane == 0) wred2[warp] = rp;

    // two-step 16-slot block reduce (halves smem)
    if (warp < 16) {
        smax[warp][lane] = mx;
#pragma unroll
        for (int q = 0; q < NMOM; ++q) smom[warp][q][lane] = m[q];
    }
    __syncthreads();
    if (warp >= 16) {
        const int s = warp - 16;
        smax[s][lane] = fmaxf(smax[s][lane], mx);
#pragma unroll
        for (int q = 0; q < NMOM; ++q) smom[s][q][lane] += m[q];
    }
    __syncthreads();

    // block sums -> PUSH to every rank's recv buffers (fire-and-forget DSMEM stores)
    if (tid < NMOM * MM) {
        const int q = tid >> 5, kk = tid & 31;
        float s0 = 0.f, s1 = 0.f, s2 = 0.f, s3 = 0.f;
#pragma unroll
        for (int i = 0; i < 16; i += 4) {
            s0 += smom[i + 0][q][kk];
            s1 += smom[i + 1][q][kk];
            s2 += smom[i + 2][q][kk];
            s3 += smom[i + 3][q][kk];
        }
        const float bs = (s0 + s1) + (s2 + s3);
#pragma unroll
        for (int r = 0; r < CLUS; ++r)
            *cluster.map_shared_rank(&recv_mom[q][kk][myrank], r) = bs;
    }
    if (tid < MM) {
        float v = smax[0][tid];
#pragma unroll
        for (int i = 1; i < 16; ++i) v = fmaxf(v, smax[i][tid]);
#pragma unroll
        for (int r = 0; r < CLUS; ++r)
            *cluster.map_shared_rank(&recv_max[tid][myrank], r) = v;
    }

    // ---------------- THE cluster barrier (split arrive/wait; rp reduce inside) -------
    asm volatile("barrier.cluster.arrive.aligned;" ::: "memory");
    float rpb = 0.0f;                      // block-level sum of rv*ev (warp 0 lane 0)
    if (warp == 0) {
        float v = wred2[lane];
#pragma unroll
        for (int o = 16; o > 0; o >>= 1) v += __shfl_down_sync(0xffffffffu, v, o);
        rpb = v;                           // valid in lane 0
    }
    asm volatile("barrier.cluster.wait.aligned;" ::: "memory");

    // ---------------- Phase 2: LOCAL coefficient build (no remote reads) --------------
    if (tid < NMOM * MM) {
        const int q = tid >> 5, kk = tid & 31;
        float s0 = 0.f, s1 = 0.f;
#pragma unroll
        for (int r = 0; r < CLUS; r += 2) {
            s0 += recv_mom[q][kk][r];
            s1 += recv_mom[q][kk][r + 1];
        }
        sM[q][kk] = s0 + s1;
    }
    if (tid < MM) {
        float v = recv_max[tid][0];
#pragma unroll
        for (int r = 1; r < CLUS; ++r) v = fmaxf(v, recv_max[tid][r]);
        float scale = 1.0f / (2.0f * sigv * sqrtf(2.0f));
        float f = scale * __expf(-v);
        float fp = 1.0f;
#pragma unroll
        for (int q = 0; q < NMOM; ++q) { sfp[q][tid] = fp; fp *= f; }
    }
    __syncthreads();
    if (tid < NMOM * MM) {                 // b_m = sum_p A[m][p] * M'_p * f^p
        const int md = tid >> 5, kk = tid & 31;
        float bm = 0.0f;
#pragma unroll
        for (int p = 0; p < NMOM; ++p) bm = fmaf(d_A[md][p], sM[p][kk] * sfp[p][kk], bm);
        sbb[md][kk] = bm;
        if (md == 0) sbb[NMOM][kk] = sM[0][kk];   // W
    }
    __syncthreads();

    // ---------------- Phase 3: eval — ONE log per thread via masked product -----------
    float bb[NMOM];
#pragma unroll
    for (int q = 0; q < NMOM; ++q) bb[q] = sbb[q][lane];
    const float W = sbb[NMOM][lane];
    const float f = sfp[1][lane];          // f^1

    float prod = 1.0f;                     // cum in [~1e3, ~2.4e3]; prod of <=8 fits fp32
#pragma unroll
    for (int e = 0; e < EPT; ++e) {
        float x = T[e] * f;
        float s = bb[NMOM - 1];
#pragma unroll
        for (int q = NMOM - 2; q >= 0; --q) s = fmaf(s, x, bb[q]);
        float cum = fmaf(0.5f, W + w[e], -s);
        prod *= fmaf(evv[e], cum - 1.0f, 1.0f);   // ev ? cum : 1 (ev is exactly 0/1)
    }
    float lacc = __logf(prod);             // = sum_e ev*log(cum)  (EPT=8: prod<=2.4e3^8? no:
                                           //  guarded below by splitting at EPT>4)
#if ((NN * MM) / (16 * TB)) != EPT        // (compile-time note only)
#endif
#pragma unroll
    for (int o = 16; o > 0; o >>= 1) lacc += __shfl_down_sync(0xffffffffu, lacc, o);
    if (lane == 0) wred[warp] = lacc;
    __syncthreads();

    if (warp == 0) {
        float v = wred[lane];
#pragma unroll
        for (int o = 16; o > 0; o >>= 1) v += __shfl_down_sync(0xffffffffu, v, o);
        if (lane == 0) {
            float block_loss = rpb - v;    // sum (rv - log cum) * ev over this CTA
            *cluster.map_shared_rank(&recv_loss[myrank], 0) = block_loss;
            asm volatile("fence.acq_rel.cluster;" ::: "memory");
            asm volatile(
                "{\n\t"
                ".reg .b32 remAddr32;\n\t"
                "mapa.shared::cluster.u32 remAddr32, %0, %1;\n\t"
                "mbarrier.arrive.shared::cluster.b64 _, [remAddr32];\n\t"
                "}"
                :: "r"(mbar_addr), "r"(0) : "memory");
        }
    }
    if (myrank != 0 || warp != 0) return;  // peers + CTA0's other warps exit early

    // ---------------- CTA 0, warp 0: wait for all arrivals, finish --------------------
    if (lane == 0) {
        uint32_t done;
        asm volatile(
            "{\n\t"
            ".reg .pred p;\n\t"
            "mbarrier.try_wait.parity.acquire.cta.shared::cta.b64 p, [%1], %2;\n\t"
            "selp.b32 %0, 1, 0, p;\n\t"
            "}"
            : "=r"(done) : "r"(mbar_addr), "r"(0u) : "memory");
        if (!done) {
            asm volatile(
                "{\n\t"
                ".reg .pred P1;\n\t"
                "WAIT_LOOP_%=:\n\t"
                "mbarrier.try_wait.parity.acquire.cta.shared::cta.b64 P1, [%0], %1, 0x989680;\n\t"
                "@P1 bra.uni WAIT_DONE_%=;\n\t"
                "bra.uni WAIT_LOOP_%=;\n\t"
                "WAIT_DONE_%=:\n\t"
                "}"
                :: "r"(mbar_addr), "r"(0u) : "memory");
        }
        asm volatile("fence.acq_rel.cluster;" ::: "memory");
    }
    __syncwarp();
    float v = (lane < CLUS) ? recv_loss[lane] : 0.0f;
#pragma unroll
    for (int o = 16; o > 0; o >>= 1) v += __shfl_down_sync(0xffffffffu, v, o);
    if (lane == 0) out[0] = -v;
}

extern "C" void kernel_launch(void* const* d_in, const int* in_sizes, int n_in,
                              void* d_out, int out_size) {
    const float* risk  = (const float*)d_in[0];
    const float* expr  = (const float*)d_in[1];
    const float* tr    = (const float*)d_in[2];
    const float* ev    = (const float*)d_in[3];
    const float* sigma = (const float*)d_in[4];
    float* out = (float*)d_out;

    // Host-side setup at capture time only (graph replays skip this). Deterministic.
    int use16 = 0;
    if (cudaFuncSetAttribute((const void*)fused<16>,
                             cudaFuncAttributeNonPortableClusterSizeAllowed, 1)
        == cudaSuccess) {
        cudaLaunchConfig_t probe = {};
        probe.gridDim  = {16, 1, 1};
        probe.blockDim = {TB, 1, 1};
        int maxC = 0;
        if (cudaOccupancyMaxPotentialClusterSize(&maxC, (const void*)fused<16>, &probe)
            == cudaSuccess && maxC >= 16)
            use16 = 1;
    }

    cudaLaunchAttribute attrs[1];
    attrs[0].id = cudaLaunchAttributeClusterDimension;
    cudaLaunchConfig_t cfg = {};
    cfg.blockDim = {TB, 1, 1};
    cfg.attrs    = attrs;
    cfg.numAttrs = 1;

    if (use16) {
        cfg.gridDim = {16, 1, 1};
        attrs[0].val.clusterDim = {16, 1, 1};
        cudaLaunchKernelEx(&cfg, fused<16>, risk, expr, tr, ev, sigma, out);
    } else {
        cfg.gridDim = {8, 1, 1};
        attrs[0].val.clusterDim = {8, 1, 1};
        cudaLaunchKernelEx(&cfg, fused<8>, risk, expr, tr, ev, sigma, out);
    }
}

// round 16
// speedup vs baseline: 1.6918x; 1.6918x over previous
#include <cuda_runtime.h>
#include <cooperative_groups.h>
#include <math.h>

namespace cg = cooperative_groups;

#define NN 2048
#define MM 32
#define NMOM 8                 // moments M_0..M_7 (degree-7 erf series)
#define TB 1024                // threads per CTA (32 warps)
#define NW 32

// A[m][p] = C[(m+p-1)/2] * binom(m+p, m) * (-1)^p for (m+p) odd <= 7, else 0.
// 0.5*erf(d) ~ C0 d + C1 d^3 + C2 d^5 + C3 d^7  (|d| <= 0.3536, trunc ~5e-7 rel)
__device__ __constant__ float d_A[NMOM][NMOM] = {
  {0.f,-0.5641895835477563f,0.f, 0.18806319451591878f,0.f,-0.05641895835477563f,0.f, 0.013433085322565627f},
  {0.5641895835477563f,0.f,-0.5641895835477563f,0.f, 0.28209479177387815f,0.f,-0.09403159725795939f,0.f},
  {0.f, 0.5641895835477563f,0.f,-0.5641895835477563f,0.f, 0.28209479177387817f,0.f,0.f},
  {-0.18806319451591878f,0.f, 0.5641895835477563f,0.f,-0.47015798628979696f,0.f,0.f,0.f},
  {0.f,-0.28209479177387815f,0.f, 0.47015798628979696f,0.f,0.f,0.f,0.f},
  {0.05641895835477563f,0.f,-0.28209479177387817f,0.f,0.f,0.f,0.f,0.f},
  {0.f, 0.09403159725795939f,0.f,0.f,0.f,0.f,0.f,0.f},
  {-0.013433085322565627f,0.f,0.f,0.f,0.f,0.f,0.f,0.f}
};

template <int CLUS>
__global__ void __launch_bounds__(TB, 1)
fused(const float* __restrict__ risk,
      const float* __restrict__ expr,
      const float* __restrict__ tr,
      const float* __restrict__ ev,
      const float* __restrict__ sigma,
      float* __restrict__ out) {
    constexpr int EPT = (NN * MM) / (CLUS * TB);   // 8 @ CLUS=8, 4 @ CLUS=16
    cg::cluster_group cluster = cg::this_cluster();
    const int tid  = threadIdx.x;
    const int warp = tid >> 5, lane = tid & 31;
    const int myrank = blockIdx.x;                 // single cluster == grid

    // published (peers read via DSMEM pull) — not modified after barrier #1
    __shared__ float pub_mom[NMOM][MM];   // this CTA's raw moment partials
    __shared__ float pub_max[MM];         // this CTA's per-column max(diff)
    __shared__ float recv_loss[16];       // CTA 0 only: loss pushed by each rank
    // private working storage
    __shared__ float smom[NW][NMOM][MM];  // 32 KB
    __shared__ float smax[NW][MM];        // 4 KB
    __shared__ float sM[NMOM][MM];        // cluster-wide raw moments
    __shared__ float sfp[NMOM][MM];       // f^q per column
    __shared__ float sbb[NMOM + 1][MM];   // b_0..b_7, row NMOM = W
    __shared__ float wred[NW], wred2[NW];

    const float sigv = sigma[0];
    const int   base = myrank * (TB * EPT) + tid;  // lane = column (stride 1024)

    // ---------------- Phase 1: moments + max + rv*ev over EPT elements ----------------
    float w[EPT], T[EPT], evv[EPT];
    float mx = -1e30f, rp = 0.0f;
    float m[NMOM];
#pragma unroll
    for (int q = 0; q < NMOM; ++q) m[q] = 0.0f;

#pragma unroll
    for (int e = 0; e < EPT; ++e) {
        const int idx = base + e * TB;
        float rv = risk[idx];
        float d  = expr[idx] - tr[idx];
        evv[e] = ev[idx];
        T[e]   = __expf(d);
        w[e]   = __expf(rv);
        mx = fmaxf(mx, d);
        rp = fmaf(rv, evv[e], rp);
        float p = w[e];
        m[0] += p;
#pragma unroll
        for (int q = 1; q < NMOM; ++q) { p *= T[e]; m[q] += p; }
    }
    // rv*ev: warp-reduce now; block-combine inside the barrier window
#pragma unroll
    for (int o = 16; o > 0; o >>= 1) rp += __shfl_down_sync(0xffffffffu, rp, o);
    if (lane == 0) wred2[warp] = rp;

    smax[warp][lane] = mx;
#pragma unroll
    for (int q = 0; q < NMOM; ++q) smom[warp][q][lane] = m[q];
    __syncthreads();

    if (tid < 32) {                        // column max over 32 warps
        float v = smax[0][tid];
#pragma unroll
        for (int i = 1; i < NW; ++i) v = fmaxf(v, smax[i][tid]);
        pub_max[tid] = v;
    }
    if (tid < NMOM * MM) {                 // moment sums over 32 warps (4-acc)
        const int q = tid >> 5, kk = tid & 31;
        float s0 = 0.f, s1 = 0.f, s2 = 0.f, s3 = 0.f;
#pragma unroll
        for (int i = 0; i < NW; i += 4) {
            s0 += smom[i + 0][q][kk];
            s1 += smom[i + 1][q][kk];
            s2 += smom[i + 2][q][kk];
            s3 += smom[i + 3][q][kk];
        }
        pub_mom[q][kk] = (s0 + s1) + (s2 + s3);
    }

    // ---------------- Cluster barrier #1 (split; rp block-reduce inside) --------------
    asm volatile("barrier.cluster.arrive.aligned;" ::: "memory");
    float rpb = 0.0f;                      // block-level sum of rv*ev (warp 0 lane 0)
    if (warp == 0) {
        float v = wred2[lane];
#pragma unroll
        for (int o = 16; o > 0; o >>= 1) v += __shfl_down_sync(0xffffffffu, v, o);
        rpb = v;
    }
    asm volatile("barrier.cluster.wait.aligned;" ::: "memory");

    // ---------------- Phase 2: coefficient build via DSMEM PULL (proven R14) ----------
    if (tid < NMOM * MM) {                 // sum this (q,k) over all CLUS CTAs
        const int q = tid >> 5, kk = tid & 31;
        float s0 = 0.f, s1 = 0.f;
#pragma unroll
        for (int r = 0; r < CLUS; r += 2) {
            const float* p0 = cluster.map_shared_rank(&pub_mom[q][kk], r);
            const float* p1 = cluster.map_shared_rank(&pub_mom[q][kk], r + 1);
            s0 += *p0; s1 += *p1;
        }
        sM[q][kk] = s0 + s1;
    }
    if (tid < 32) {                        // cluster max -> f and its powers
        float v = -1e30f;
#pragma unroll
        for (int r = 0; r < CLUS; ++r) {
            const float* p = cluster.map_shared_rank(&pub_max[tid], r);
            v = fmaxf(v, *p);
        }
        float scale = 1.0f / (2.0f * sigv * sqrtf(2.0f));
        float f = scale * __expf(-v);
        float fp = 1.0f;
#pragma unroll
        for (int q = 0; q < NMOM; ++q) { sfp[q][tid] = fp; fp *= f; }
    }
    __syncthreads();
    if (tid < NMOM * MM) {                 // b_m = sum_p A[m][p] * M'_p * f^p
        const int md = tid >> 5, kk = tid & 31;
        float bm = 0.0f;
#pragma unroll
        for (int p = 0; p < NMOM; ++p) bm = fmaf(d_A[md][p], sM[p][kk] * sfp[p][kk], bm);
        sbb[md][kk] = bm;
        if (md == 0) sbb[NMOM][kk] = sM[0][kk];   // W
    }
    __syncthreads();

    // ---------------- Phase 3: eval (w, T, evv live; rv folded into rpb) --------------
    float bb[NMOM];
#pragma unroll
    for (int q = 0; q < NMOM; ++q) bb[q] = sbb[q][lane];
    const float W = sbb[NMOM][lane];
    const float f = sfp[1][lane];          // f^1

    float acc = 0.0f;                      // sum_e ev * log(cum)
#pragma unroll
    for (int e = 0; e < EPT; ++e) {
        float x = T[e] * f;
        float s = bb[NMOM - 1];
#pragma unroll
        for (int q = NMOM - 2; q >= 0; --q) s = fmaf(s, x, bb[q]);
        float cum = fmaf(0.5f, W + w[e], -s);
        acc = fmaf(evv[e], __logf(cum), acc);
    }
#pragma unroll
    for (int o = 16; o > 0; o >>= 1) acc += __shfl_down_sync(0xffffffffu, acc, o);
    if (lane == 0) wred[warp] = acc;
    __syncthreads();

    // warp 0: block loss = rpb - sum(ev*log cum); PUSH one float into CTA 0
    if (warp == 0) {
        float v = wred[lane];
#pragma unroll
        for (int o = 16; o > 0; o >>= 1) v += __shfl_down_sync(0xffffffffu, v, o);
        if (lane == 0) {
            float block_loss = rpb - v;
            *cluster.map_shared_rank(&recv_loss[myrank], 0) = block_loss;
        }
    }

    // ---------------- Cluster barrier #2: orders the 16 loss pushes ----------------
    // (barrier.cluster.arrive has release semantics; wait has acquire — the remote
    //  stores above are visible to CTA 0 after this sync. No remote access follows,
    //  so peers may exit immediately: no third barrier needed.)
    cluster.sync();

    if (myrank == 0 && warp == 0) {
        float v = (lane < CLUS) ? recv_loss[lane] : 0.0f;
#pragma unroll
        for (int o = 16; o > 0; o >>= 1) v += __shfl_down_sync(0xffffffffu, v, o);
        if (lane == 0) out[0] = -v;
    }
}

extern "C" void kernel_launch(void* const* d_in, const int* in_sizes, int n_in,
                              void* d_out, int out_size) {
    const float* risk  = (const float*)d_in[0];
    const float* expr  = (const float*)d_in[1];
    const float* tr    = (const float*)d_in[2];
    const float* ev    = (const float*)d_in[3];
    const float* sigma = (const float*)d_in[4];
    float* out = (float*)d_out;

    // Host-side setup at capture time only (graph replays skip this). Deterministic.
    int use16 = 0;
    if (cudaFuncSetAttribute((const void*)fused<16>,
                             cudaFuncAttributeNonPortableClusterSizeAllowed, 1)
        == cudaSuccess) {
        cudaLaunchConfig_t probe = {};
        probe.gridDim  = {16, 1, 1};
        probe.blockDim = {TB, 1, 1};
        int maxC = 0;
        if (cudaOccupancyMaxPotentialClusterSize(&maxC, (const void*)fused<16>, &probe)
            == cudaSuccess && maxC >= 16)
            use16 = 1;
    }

    cudaLaunchAttribute attrs[1];
    attrs[0].id = cudaLaunchAttributeClusterDimension;
    cudaLaunchConfig_t cfg = {};
    cfg.blockDim = {TB, 1, 1};
    cfg.attrs    = attrs;
    cfg.numAttrs = 1;

    if (use16) {
        cfg.gridDim = {16, 1, 1};
        attrs[0].val.clusterDim = {16, 1, 1};
        cudaLaunchKernelEx(&cfg, fused<16>, risk, expr, tr, ev, sigma, out);
    } else {
        cfg.gridDim = {8, 1, 1};
        attrs[0].val.clusterDim = {8, 1, 1};
        cudaLaunchKernelEx(&cfg, fused<8>, risk, expr, tr, ev, sigma, out);
    }
}